// round 14
// baseline (speedup 1.0000x reference)
#include <cuda_runtime.h>
#include <math.h>
#include <stdint.h>

#define SEQ 2048
#define DIM 1280
#define NH  16
#define HD  80
#define DIMP 1296            // padded weight rows (9 uniform 144-col tiles)
#define RBX (SEQ / 16)       // 128 row-blocks of 16
#define KBX (DIM / 8)        // 160 k-blocks of 8
#define CBW (DIMP / 8)       // 162 col-blocks of 8 (padded)

// Scratch (device globals)
__device__ float g_Q[SEQ * DIM];
__device__ float g_K[SEQ * DIM];
__device__ float g_Vt[SEQ * DIM];     // V transposed [DIM][SEQ], tf32-rounded
__device__ float g_Xap[SEQ * DIM];    // X in A-fragment order, tf32
__device__ float g_Aap[SEQ * DIM];    // attention out in A-fragment order, tf32
__device__ float g_Wqp[DIMP * DIM];   // weights in B-fragment order, tf32
__device__ float g_Wkp[DIMP * DIM];
__device__ float g_Wvp[DIMP * DIM];
__device__ float g_Wop[DIMP * DIM];

__device__ __forceinline__ float f2tf32(float x) {
    uint32_t u;
    asm("cvt.rna.tf32.f32 %0, %1;" : "=r"(u) : "f"(x));
    return __uint_as_float(u);
}

__device__ __forceinline__ void mma_tf32(float* c, const uint32_t* a, const uint32_t* b) {
    asm("mma.sync.aligned.m16n8k8.row.col.f32.tf32.tf32.f32 "
        "{%0,%1,%2,%3}, {%4,%5,%6,%7}, {%8,%9}, {%0,%1,%2,%3};"
        : "+f"(c[0]), "+f"(c[1]), "+f"(c[2]), "+f"(c[3])
        : "r"(a[0]), "r"(a[1]), "r"(a[2]), "r"(a[3]), "r"(b[0]), "r"(b[1]));
}

__device__ __forceinline__ void cp16(uint32_t dst, const void* src) {
    asm volatile("cp.async.cg.shared.global [%0], [%1], 16;\n" :: "r"(dst), "l"(src));
}
__device__ __forceinline__ void cp16z(uint32_t dst, const void* src, int bytes) {
    asm volatile("cp.async.cg.shared.global [%0], [%1], 16, %2;\n"
                 :: "r"(dst), "l"(src), "r"(bytes));
}

// ---------------------------------------------------------------------------
// permute_all: X -> A-fragment order; weights -> B-fragment order (tf32).
// ---------------------------------------------------------------------------
#define NXP (RBX * KBX * 32)     // 655360 float4 outputs
#define NWP (CBW * KBX * 32)     // 829440 float2 outputs per weight
__global__ void permute_all(const float* __restrict__ X,
                            const float* __restrict__ Wq, const float* __restrict__ Wk,
                            const float* __restrict__ Wv, const float* __restrict__ Wo)
{
    int i = blockIdx.x * blockDim.x + threadIdx.x;
    if (i < NXP) {
        int lane = i & 31, t = i >> 5;
        int kb = t % KBX, rb = t / KBX;
        int g = lane >> 2, tg = lane & 3;
        int r = rb * 16 + g, c = kb * 8 + tg;
        float4 v;
        v.x = f2tf32(X[(size_t)r * DIM + c]);
        v.y = f2tf32(X[(size_t)(r + 8) * DIM + c]);
        v.z = f2tf32(X[(size_t)r * DIM + c + 4]);
        v.w = f2tf32(X[(size_t)(r + 8) * DIM + c + 4]);
        ((float4*)g_Xap)[i] = v;
        return;
    }
    int j = i - NXP;
    int widx = j / NWP;
    if (widx >= 4) return;
    int k = j - widx * NWP;
    const float* W = (widx == 0) ? Wq : (widx == 1) ? Wk : (widx == 2) ? Wv : Wo;
    float* dst = (widx == 0) ? g_Wqp : (widx == 1) ? g_Wkp : (widx == 2) ? g_Wvp : g_Wop;
    int lane = k & 31, t = k >> 5;
    int kb = t % KBX, cb = t / KBX;
    int g = lane >> 2, tg = lane & 3;
    int r = cb * 8 + g, c = kb * 8 + tg;
    float2 v;
    if (r < DIM) {
        v.x = f2tf32(W[(size_t)r * DIM + c]);
        v.y = f2tf32(W[(size_t)r * DIM + c + 4]);
    } else {
        v = make_float2(0.f, 0.f);
    }
    ((float2*)dst)[k] = v;
}

// ---------------------------------------------------------------------------
// TF32 GEMM (NT), fragment-order operands, 3-stage cp.async pipeline with
// ONE __syncthreads per iteration: wait_group -> sync -> issue(ti+2) ->
// compute(ti). Visibility: every thread retires group ti before the sync, so
// after the sync all copies of tile ti are visible to all warps; issue(ti+2)
// writes stage (ti-1)%3, whose readers (compute(ti-1)) are past the sync.
// BM=128, BN=144 -> 144 CTAs; 8 warps (4m x 2n), warp tile 32x72.
// ---------------------------------------------------------------------------
#define BM 128
#define BN 144
#define BK 32
#define A_STAGE (8 * 4 * 128)     // 4096 floats
#define B_STAGE (18 * 4 * 64)     // 4608 floats
#define STAGEF (A_STAGE + B_STAGE)
#define GEMM_SMEM (3 * STAGEF * 4)  // 104448 B

template<bool TRANS>
__global__ __launch_bounds__(256, 1)
void gemm_tf32_frag(const float* __restrict__ Aap, const float* __restrict__ Bbp,
                    const float* __restrict__ bias, float* __restrict__ C,
                    int M, int N)
{
    extern __shared__ float sm[];
    const int tid = threadIdx.x;
    const int m0 = blockIdx.y * BM;
    const int n0 = blockIdx.x * BN;
    const int rb0 = m0 >> 4;
    const int cb0 = blockIdx.x * 18;

    const int warp = tid >> 5, lane = tid & 31;
    const int wm = warp >> 1, wn = warp & 1;
    const int g = lane >> 2, tg = lane & 3;

    const uint32_t sbase = (uint32_t)__cvta_generic_to_shared(sm);

    float acc[2][9][4];
#pragma unroll
    for (int mt = 0; mt < 2; mt++)
#pragma unroll
        for (int nt = 0; nt < 9; nt++)
#pragma unroll
            for (int r = 0; r < 4; r++) acc[mt][nt][r] = 0.f;

    const int T = DIM / BK;   // 40

    auto issue = [&](int stage, int kt) {
        const int kb0 = kt >> 3;
        const uint32_t base = sbase + (uint32_t)stage * STAGEF * 4u;
#pragma unroll
        for (int t = 0; t < 4; t++) {          // A: 1024 16B-chunks
            int ci = tid + t * 256;
            int blk = ci >> 5;
            int rb_l = blk >> 2, kb_l = blk & 3;
            int l16 = ci & 31;
            cp16(base + (uint32_t)(blk * 128 + l16 * 4) * 4u,
                 Aap + ((size_t)(rb0 + rb_l) * KBX + kb0 + kb_l) * 128 + l16 * 4);
        }
#pragma unroll
        for (int t = 0; t < 5; t++) {          // B: 1152 16B-chunks
            int ci = tid + t * 256;
            if (ci < 1152) {
                int blk = ci >> 4;
                int cb_l = blk >> 2, kb_l = blk & 3;
                int l16 = ci & 15;
                cp16(base + (uint32_t)(A_STAGE + blk * 64 + l16 * 4) * 4u,
                     Bbp + ((size_t)(cb0 + cb_l) * KBX + kb0 + kb_l) * 64 + l16 * 4);
            }
        }
        asm volatile("cp.async.commit_group;\n");
    };

    auto loadA = [&](const float* Asr, int ks, uint32_t af[2][4]) {
#pragma unroll
        for (int mt = 0; mt < 2; mt++) {
            float4 v = *(const float4*)(Asr + ((wm * 2 + mt) * 4 + ks) * 128 + lane * 4);
            af[mt][0] = __float_as_uint(v.x);
            af[mt][1] = __float_as_uint(v.y);
            af[mt][2] = __float_as_uint(v.z);
            af[mt][3] = __float_as_uint(v.w);
        }
    };
    auto loadB = [&](const float* Bsr, int ks, uint32_t bf[9][2]) {
#pragma unroll
        for (int nt = 0; nt < 9; nt++) {
            float2 v = *(const float2*)(Bsr + ((wn * 9 + nt) * 4 + ks) * 64 + lane * 2);
            bf[nt][0] = __float_as_uint(v.x);
            bf[nt][1] = __float_as_uint(v.y);
        }
    };

    // Prologue: two tiles in flight.
    issue(0, 0);
    issue(1, BK);

    for (int ti = 0; ti < T; ti++) {
        if (ti + 1 < T) {
            asm volatile("cp.async.wait_group 1;\n");   // tile ti retired (this thread)
        } else {
            asm volatile("cp.async.wait_group 0;\n");
        }
        __syncthreads();                                // tile ti visible to ALL warps
        if (ti + 2 < T) {
            issue((ti + 2) % 3, (ti + 2) * BK);         // writes stage (ti-1)%3: safe
        }

        const float* Asr = sm + (ti % 3) * STAGEF;
        const float* Bsr = Asr + A_STAGE;

        uint32_t afa[2][4], bfa[9][2], afb[2][4], bfb[9][2];
        loadA(Asr, 0, afa);
        loadB(Bsr, 0, bfa);
#pragma unroll
        for (int ks = 0; ks < 4; ks++) {
            uint32_t (*afc)[4] = (ks & 1) ? afb : afa;
            uint32_t (*bfc)[2] = (ks & 1) ? bfb : bfa;
            uint32_t (*afn)[4] = (ks & 1) ? afa : afb;
            uint32_t (*bfn)[2] = (ks & 1) ? bfa : bfb;
            if (ks < 3) {
                loadA(Asr, ks + 1, afn);
                loadB(Bsr, ks + 1, bfn);
            }
#pragma unroll
            for (int mt = 0; mt < 2; mt++)
#pragma unroll
                for (int nt = 0; nt < 9; nt++)
                    mma_tf32(acc[mt][nt], afc[mt], bfc[nt]);
        }
    }

    // Epilogue with column guards (tiles may overhang N=1280).
#pragma unroll
    for (int mt = 0; mt < 2; mt++) {
#pragma unroll
        for (int nt = 0; nt < 9; nt++) {
            int r = m0 + wm * 32 + mt * 16 + g;
            int c = n0 + wn * 72 + nt * 8 + 2 * tg;
            float b0 = (c < N)     ? bias[c]     : 0.f;
            float b1 = (c + 1 < N) ? bias[c + 1] : 0.f;
            if (!TRANS) {
                if (c < N) {
                    C[(size_t)r * N + c]       = acc[mt][nt][0] + b0;
                    C[(size_t)(r + 8) * N + c] = acc[mt][nt][2] + b0;
                }
                if (c + 1 < N) {
                    C[(size_t)r * N + c + 1]       = acc[mt][nt][1] + b1;
                    C[(size_t)(r + 8) * N + c + 1] = acc[mt][nt][3] + b1;
                }
            } else {
                if (c < N) {
                    C[(size_t)c * M + r]     = f2tf32(acc[mt][nt][0] + b0);
                    C[(size_t)c * M + r + 8] = f2tf32(acc[mt][nt][2] + b0);
                }
                if (c + 1 < N) {
                    C[(size_t)(c + 1) * M + r]     = f2tf32(acc[mt][nt][1] + b1);
                    C[(size_t)(c + 1) * M + r + 8] = f2tf32(acc[mt][nt][3] + b1);
                }
            }
        }
    }
}

// ---------------------------------------------------------------------------
// RoPE in place on g_Q / g_K, float4-vectorized. Q pre-scaled; tf32-rounded.
// ---------------------------------------------------------------------------
__global__ void rope_kernel(const float* __restrict__ cs, const float* __restrict__ sn)
{
    int idx = blockIdx.x * blockDim.x + threadIdx.x;
    const int total = SEQ * NH * 10;
    if (idx >= total) return;
    int j4 = (idx % 10) * 4;
    int h = (idx / 10) % NH;
    int s = idx / (10 * NH);
    int base = s * DIM + h * HD;
    const float scale = rsqrtf((float)HD);

    float4 c0 = *(const float4*)(cs + s * HD + j4);
    float4 c1 = *(const float4*)(cs + s * HD + j4 + 40);
    float4 s0 = *(const float4*)(sn + s * HD + j4);
    float4 s1 = *(const float4*)(sn + s * HD + j4 + 40);

    {
        float4 x0 = *(const float4*)(g_Q + base + j4);
        float4 x1 = *(const float4*)(g_Q + base + j4 + 40);
        float4 o0, o1;
        o0.x = f2tf32((x0.x * c0.x - x1.x * s0.x) * scale);
        o0.y = f2tf32((x0.y * c0.y - x1.y * s0.y) * scale);
        o0.z = f2tf32((x0.z * c0.z - x1.z * s0.z) * scale);
        o0.w = f2tf32((x0.w * c0.w - x1.w * s0.w) * scale);
        o1.x = f2tf32((x1.x * c1.x + x0.x * s1.x) * scale);
        o1.y = f2tf32((x1.y * c1.y + x0.y * s1.y) * scale);
        o1.z = f2tf32((x1.z * c1.z + x0.z * s1.z) * scale);
        o1.w = f2tf32((x1.w * c1.w + x0.w * s1.w) * scale);
        *(float4*)(g_Q + base + j4)      = o0;
        *(float4*)(g_Q + base + j4 + 40) = o1;
    }
    {
        float4 x0 = *(const float4*)(g_K + base + j4);
        float4 x1 = *(const float4*)(g_K + base + j4 + 40);
        float4 o0, o1;
        o0.x = f2tf32(x0.x * c0.x - x1.x * s0.x);
        o0.y = f2tf32(x0.y * c0.y - x1.y * s0.y);
        o0.z = f2tf32(x0.z * c0.z - x1.z * s0.z);
        o0.w = f2tf32(x0.w * c0.w - x1.w * s0.w);
        o1.x = f2tf32(x1.x * c1.x + x0.x * s1.x);
        o1.y = f2tf32(x1.y * c1.y + x0.y * s1.y);
        o1.z = f2tf32(x1.z * c1.z + x0.z * s1.z);
        o1.w = f2tf32(x1.w * c1.w + x0.w * s1.w);
        *(float4*)(g_K + base + j4)      = o0;
        *(float4*)(g_K + base + j4 + 40) = o1;
    }
}

// ---------------------------------------------------------------------------
// Persistent segmented flash attention (proven core). Epilogue writes the
// output in A-fragment order to g_Aap via a warp-private bounce through Qs.
// ---------------------------------------------------------------------------
#define ATT_GRID 296
#define QS_STR 84
#define VT_STR 68
#define AT_KS  (64 * QS_STR)
#define AT_VT  (2 * 64 * QS_STR)
#define AT_PS  (AT_VT + 80 * VT_STR)
#define ATTN_SMEM ((AT_PS + 64 * VT_STR) * 4)   // 82176 B

__global__ __launch_bounds__(128)
void attn_mma(const int* __restrict__ cu)
{
    extern __shared__ float sm[];
    float* Qs = sm;
    float* Ks = sm + AT_KS;
    float* Vt = sm + AT_VT;
    float* Ps = sm + AT_PS;

    const uint32_t sQ = (uint32_t)__cvta_generic_to_shared(Qs);
    const uint32_t sK = (uint32_t)__cvta_generic_to_shared(Ks);
    const uint32_t sV = (uint32_t)__cvta_generic_to_shared(Vt);

    const int tid = threadIdx.x;
    const int warp = tid >> 5, lane = tid & 31;
    const int g = lane >> 2, tg = lane & 3;
    const int m0 = warp * 16;

    for (int item = blockIdx.x; item < (SEQ / 64) * NH; item += ATT_GRID) {
        const int qb = (item >> 4) * 64;
        const int h  = item & 15;

        int ks = 0, ke = SEQ;
#pragma unroll
        for (int i = 0; i < 4; i++)
            if (qb >= cu[i] && qb < cu[i + 1]) { ks = cu[i]; ke = cu[i + 1]; }

        __syncthreads();

#pragma unroll
        for (int t = 0; t < 10; t++) {
            int idx = tid + t * 128;
            int r = idx / 20, dc = (idx % 20) * 4;
            cp16(sQ + (uint32_t)(r * QS_STR + dc) * 4u,
                 g_Q + (size_t)(qb + r) * DIM + h * HD + dc);
        }
        asm volatile("cp.async.commit_group;\n");
        {
            int kn0 = min(64, ke - ks);
#pragma unroll
            for (int t = 0; t < 10; t++) {
                int idx = tid + t * 128;
                int r = idx / 20, dc = (idx % 20) * 4;
                int srow = (r < kn0) ? (ks + r) : ks;
                cp16z(sK + (uint32_t)(r * QS_STR + dc) * 4u,
                      g_K + (size_t)srow * DIM + h * HD + dc, (r < kn0) ? 16 : 0);
            }
            asm volatile("cp.async.commit_group;\n");
        }

        float mrow[2] = {-1e30f, -1e30f};
        float lrow[2] = {0.f, 0.f};
        float o[10][4];
#pragma unroll
        for (int nt = 0; nt < 10; nt++)
#pragma unroll
            for (int r = 0; r < 4; r++) o[nt][r] = 0.f;

        for (int kt = ks; kt < ke; kt += 64) {
            int kn = min(64, ke - kt);
            asm volatile("cp.async.wait_group 0;\n");
            __syncthreads();

#pragma unroll
            for (int t = 0; t < 10; t++) {
                int idx = tid + t * 128;
                int d = idx >> 4, kc = (idx & 15) * 4;
                int bytes = min(max(kn - kc, 0), 4) * 4;
                int scol = (kc < kn) ? (kt + kc) : kt;
                cp16z(sV + (uint32_t)(d * VT_STR + kc) * 4u,
                      g_Vt + (size_t)(h * HD + d) * SEQ + scol, bytes);
            }
            asm volatile("cp.async.commit_group;\n");

            float sacc[8][4];
#pragma unroll
            for (int nt = 0; nt < 8; nt++)
#pragma unroll
                for (int r = 0; r < 4; r++) sacc[nt][r] = 0.f;

#pragma unroll
            for (int ksp = 0; ksp < 10; ksp++) {
                const int k0 = ksp * 8;
                uint32_t af[4], bf[8][2];
                af[0] = __float_as_uint(Qs[(m0 + g) * QS_STR + k0 + tg]);
                af[1] = __float_as_uint(Qs[(m0 + 8 + g) * QS_STR + k0 + tg]);
                af[2] = __float_as_uint(Qs[(m0 + g) * QS_STR + k0 + tg + 4]);
                af[3] = __float_as_uint(Qs[(m0 + 8 + g) * QS_STR + k0 + tg + 4]);
#pragma unroll
                for (int nt = 0; nt < 8; nt++) {
                    bf[nt][0] = __float_as_uint(Ks[(nt * 8 + g) * QS_STR + k0 + tg]);
                    bf[nt][1] = __float_as_uint(Ks[(nt * 8 + g) * QS_STR + k0 + tg + 4]);
                }
#pragma unroll
                for (int nt = 0; nt < 8; nt++)
                    mma_tf32(sacc[nt], af, bf[nt]);
            }

            __syncthreads();

            if (kt + 64 < ke) {
                int knn = min(64, ke - (kt + 64));
#pragma unroll
                for (int t = 0; t < 10; t++) {
                    int idx = tid + t * 128;
                    int r = idx / 20, dc = (idx % 20) * 4;
                    int srow = (r < knn) ? (kt + 64 + r) : (kt + 64 - 1);
                    cp16z(sK + (uint32_t)(r * QS_STR + dc) * 4u,
                          g_K + (size_t)srow * DIM + h * HD + dc, (r < knn) ? 16 : 0);
                }
            }
            asm volatile("cp.async.commit_group;\n");

            if (kn < 64) {
#pragma unroll
                for (int nt = 0; nt < 8; nt++) {
                    int c = nt * 8 + 2 * tg;
                    if (c >= kn)     { sacc[nt][0] = -1e30f; sacc[nt][2] = -1e30f; }
                    if (c + 1 >= kn) { sacc[nt][1] = -1e30f; sacc[nt][3] = -1e30f; }
                }
            }

#pragma unroll
            for (int half = 0; half < 2; half++) {
                const int b = half * 2;
                float mloc = -1e30f;
#pragma unroll
                for (int nt = 0; nt < 8; nt++)
                    mloc = fmaxf(mloc, fmaxf(sacc[nt][b], sacc[nt][b + 1]));
                mloc = fmaxf(mloc, __shfl_xor_sync(0xffffffffu, mloc, 1));
                mloc = fmaxf(mloc, __shfl_xor_sync(0xffffffffu, mloc, 2));
                float mn = fmaxf(mrow[half], mloc);
                float fac = __expf(mrow[half] - mn);
                mrow[half] = mn;
                float rs = 0.f;
#pragma unroll
                for (int nt = 0; nt < 8; nt++) {
                    float p0 = __expf(sacc[nt][b] - mn);
                    float p1 = __expf(sacc[nt][b + 1] - mn);
                    sacc[nt][b] = p0; sacc[nt][b + 1] = p1;
                    rs += p0 + p1;
                }
                rs += __shfl_xor_sync(0xffffffffu, rs, 1);
                rs += __shfl_xor_sync(0xffffffffu, rs, 2);
                lrow[half] = lrow[half] * fac + rs;
#pragma unroll
                for (int nt = 0; nt < 10; nt++) { o[nt][b] *= fac; o[nt][b + 1] *= fac; }
            }

#pragma unroll
            for (int nt = 0; nt < 8; nt++) {
                int c = nt * 8 + 2 * tg;
                Ps[(m0 + g) * VT_STR + c]         = f2tf32(sacc[nt][0]);
                Ps[(m0 + g) * VT_STR + c + 1]     = f2tf32(sacc[nt][1]);
                Ps[(m0 + 8 + g) * VT_STR + c]     = f2tf32(sacc[nt][2]);
                Ps[(m0 + 8 + g) * VT_STR + c + 1] = f2tf32(sacc[nt][3]);
            }

            asm volatile("cp.async.wait_group 1;\n");
            __syncthreads();

#pragma unroll
            for (int ksp = 0; ksp < 8; ksp++) {
                const int k0 = ksp * 8;
                uint32_t af[4], bf[10][2];
                af[0] = __float_as_uint(Ps[(m0 + g) * VT_STR + k0 + tg]);
                af[1] = __float_as_uint(Ps[(m0 + 8 + g) * VT_STR + k0 + tg]);
                af[2] = __float_as_uint(Ps[(m0 + g) * VT_STR + k0 + tg + 4]);
                af[3] = __float_as_uint(Ps[(m0 + 8 + g) * VT_STR + k0 + tg + 4]);
#pragma unroll
                for (int nt = 0; nt < 10; nt++) {
                    bf[nt][0] = __float_as_uint(Vt[(nt * 8 + g) * VT_STR + k0 + tg]);
                    bf[nt][1] = __float_as_uint(Vt[(nt * 8 + g) * VT_STR + k0 + tg + 4]);
                }
#pragma unroll
                for (int nt = 0; nt < 10; nt++)
                    mma_tf32(o[nt], af, bf[nt]);
            }
        }

        // Epilogue: normalize, bounce through warp-private Qs rows, then write
        // A-fragment-order float4 to g_Aap (tf32-rounded).
        const float inv0 = 1.f / lrow[0];
        const float inv1 = 1.f / lrow[1];
#pragma unroll
        for (int nt = 0; nt < 10; nt++) {
            int c = nt * 8 + 2 * tg;
            Qs[(m0 + g) * QS_STR + c]         = o[nt][0] * inv0;
            Qs[(m0 + g) * QS_STR + c + 1]     = o[nt][1] * inv0;
            Qs[(m0 + 8 + g) * QS_STR + c]     = o[nt][2] * inv1;
            Qs[(m0 + 8 + g) * QS_STR + c + 1] = o[nt][3] * inv1;
        }
        __syncwarp();

        const int rb = (qb + m0) >> 4;
#pragma unroll
        for (int nt = 0; nt < 10; nt++) {
            int kb = h * 10 + nt;
            float4 v;
            v.x = f2tf32(Qs[(m0 + g) * QS_STR + nt * 8 + tg]);
            v.y = f2tf32(Qs[(m0 + 8 + g) * QS_STR + nt * 8 + tg]);
            v.z = f2tf32(Qs[(m0 + g) * QS_STR + nt * 8 + tg + 4]);
            v.w = f2tf32(Qs[(m0 + 8 + g) * QS_STR + nt * 8 + tg + 4]);
            ((float4*)g_Aap)[(size_t)(rb * KBX + kb) * 32 + lane] = v;
        }
        __syncwarp();
    }
}

// ---------------------------------------------------------------------------
extern "C" void kernel_launch(void* const* d_in, const int* in_sizes, int n_in,
                              void* d_out, int out_size)
{
    const float* X  = (const float*)d_in[0];
    const float* Wq = (const float*)d_in[1];
    const float* bq = (const float*)d_in[2];
    const float* Wk = (const float*)d_in[3];
    const float* bk = (const float*)d_in[4];
    const float* Wv = (const float*)d_in[5];
    const float* bv = (const float*)d_in[6];
    const float* Wo = (const float*)d_in[7];
    const float* bo = (const float*)d_in[8];
    const float* cs = (const float*)d_in[9];
    const float* sn = (const float*)d_in[10];
    const int*   cu = (const int*)d_in[11];
    float* out = (float*)d_out;

    void *pQ, *pK, *pVt, *pXap, *pAap, *pWq, *pWk, *pWv, *pWo;
    cudaGetSymbolAddress(&pQ, g_Q);
    cudaGetSymbolAddress(&pK, g_K);
    cudaGetSymbolAddress(&pVt, g_Vt);
    cudaGetSymbolAddress(&pXap, g_Xap);
    cudaGetSymbolAddress(&pAap, g_Aap);
    cudaGetSymbolAddress(&pWq, g_Wqp);
    cudaGetSymbolAddress(&pWk, g_Wkp);
    cudaGetSymbolAddress(&pWv, g_Wvp);
    cudaGetSymbolAddress(&pWo, g_Wop);

    cudaFuncSetAttribute(gemm_tf32_frag<false>,
                         cudaFuncAttributeMaxDynamicSharedMemorySize, GEMM_SMEM);
    cudaFuncSetAttribute(gemm_tf32_frag<true>,
                         cudaFuncAttributeMaxDynamicSharedMemorySize, GEMM_SMEM);
    cudaFuncSetAttribute(attn_mma,
                         cudaFuncAttributeMaxDynamicSharedMemorySize, ATTN_SMEM);

    const int ntot = NXP + 4 * NWP;
    dim3 gg(DIMP / BN, SEQ / BM);      // (9, 16) = 144 CTAs
    dim3 gb(256);

    permute_all<<<(ntot + 255) / 256, 256>>>(X, Wq, Wk, Wv, Wo);

    gemm_tf32_frag<false><<<gg, gb, GEMM_SMEM>>>((const float*)pXap, (const float*)pWq, bq, (float*)pQ, SEQ, DIM);
    gemm_tf32_frag<false><<<gg, gb, GEMM_SMEM>>>((const float*)pXap, (const float*)pWk, bk, (float*)pK, SEQ, DIM);
    gemm_tf32_frag<true ><<<gg, gb, GEMM_SMEM>>>((const float*)pXap, (const float*)pWv, bv, (float*)pVt, SEQ, DIM);

    int rope_total = SEQ * NH * 10;
    rope_kernel<<<(rope_total + 255) / 256, 256>>>(cs, sn);

    attn_mma<<<ATT_GRID, 128, ATTN_SMEM>>>(cu);

    gemm_tf32_frag<false><<<gg, gb, GEMM_SMEM>>>((const float*)pAap, (const float*)pWo, bo, out, SEQ, DIM);
}

// round 15
// speedup vs baseline: 1.0177x; 1.0177x over previous
#include <cuda_runtime.h>
#include <math.h>
#include <stdint.h>

#define SEQ 2048
#define DIM 1280
#define NH  16
#define HD  80
#define DIMP 1296            // padded weight rows (9 uniform 144-col tiles)
#define RBX (SEQ / 16)       // 128 row-blocks of 16
#define KBX (DIM / 8)        // 160 k-blocks of 8
#define CBW (DIMP / 8)       // 162 col-blocks of 8 (padded)

// Scratch (device globals)
__device__ float g_Q[SEQ * DIM];
__device__ float g_K[SEQ * DIM];
__device__ float g_Vt[SEQ * DIM];       // V transposed [DIM][SEQ], tf32
__device__ float g_Xap[SEQ * DIM];      // X in A-fragment order, tf32
__device__ float g_Aap[SEQ * DIM];      // attention out in A-fragment order, tf32
__device__ float g_Wqkvp[3 * DIMP * DIM]; // Wq|Wk|Wv stacked, B-fragment order
__device__ float g_Wop[DIMP * DIM];

__device__ __forceinline__ float f2tf32(float x) {
    uint32_t u;
    asm("cvt.rna.tf32.f32 %0, %1;" : "=r"(u) : "f"(x));
    return __uint_as_float(u);
}

__device__ __forceinline__ void mma_tf32(float* c, const uint32_t* a, const uint32_t* b) {
    asm("mma.sync.aligned.m16n8k8.row.col.f32.tf32.tf32.f32 "
        "{%0,%1,%2,%3}, {%4,%5,%6,%7}, {%8,%9}, {%0,%1,%2,%3};"
        : "+f"(c[0]), "+f"(c[1]), "+f"(c[2]), "+f"(c[3])
        : "r"(a[0]), "r"(a[1]), "r"(a[2]), "r"(a[3]), "r"(b[0]), "r"(b[1]));
}

__device__ __forceinline__ void cp16(uint32_t dst, const void* src) {
    asm volatile("cp.async.cg.shared.global [%0], [%1], 16;\n" :: "r"(dst), "l"(src));
}
__device__ __forceinline__ void cp16z(uint32_t dst, const void* src, int bytes) {
    asm volatile("cp.async.cg.shared.global [%0], [%1], 16, %2;\n"
                 :: "r"(dst), "l"(src), "r"(bytes));
}

// ---------------------------------------------------------------------------
// permute_all: X -> A-fragment order; Wq/Wk/Wv -> stacked B-fragment order;
// Wo -> B-fragment order. All tf32-rounded; weight pad rows zeroed.
// ---------------------------------------------------------------------------
#define NXP (RBX * KBX * 32)     // 655360 float4 outputs
#define NWP (CBW * KBX * 32)     // 829440 float2 outputs per weight
__global__ void permute_all(const float* __restrict__ X,
                            const float* __restrict__ Wq, const float* __restrict__ Wk,
                            const float* __restrict__ Wv, const float* __restrict__ Wo)
{
    int i = blockIdx.x * blockDim.x + threadIdx.x;
    if (i < NXP) {
        int lane = i & 31, t = i >> 5;
        int kb = t % KBX, rb = t / KBX;
        int g = lane >> 2, tg = lane & 3;
        int r = rb * 16 + g, c = kb * 8 + tg;
        float4 v;
        v.x = f2tf32(X[(size_t)r * DIM + c]);
        v.y = f2tf32(X[(size_t)(r + 8) * DIM + c]);
        v.z = f2tf32(X[(size_t)r * DIM + c + 4]);
        v.w = f2tf32(X[(size_t)(r + 8) * DIM + c + 4]);
        ((float4*)g_Xap)[i] = v;
        return;
    }
    int j = i - NXP;
    int widx = j / NWP;
    if (widx >= 4) return;
    int k = j - widx * NWP;
    const float* W = (widx == 0) ? Wq : (widx == 1) ? Wk : (widx == 2) ? Wv : Wo;
    float* dst = (widx < 3) ? (g_Wqkvp + (size_t)widx * DIMP * DIM) : g_Wop;
    int lane = k & 31, t = k >> 5;
    int kb = t % KBX, cb = t / KBX;
    int g = lane >> 2, tg = lane & 3;
    int r = cb * 8 + g, c = kb * 8 + tg;
    float2 v;
    if (r < DIM) {
        v.x = f2tf32(W[(size_t)r * DIM + c]);
        v.y = f2tf32(W[(size_t)r * DIM + c + 4]);
    } else {
        v = make_float2(0.f, 0.f);
    }
    ((float2*)dst)[k] = v;
}

// ---------------------------------------------------------------------------
// Shared GEMM mainloop machinery (R13-proven 2-stage structure:
// issue -> wait -> sync -> compute -> sync). Fragment-order operands.
// BM=128, BN=144; 8 warps (4m x 2n), warp tile 32x72, acc[2][9][4].
// ---------------------------------------------------------------------------
#define BM 128
#define BN 144
#define BK 32
#define A_STAGE (8 * 4 * 128)     // 4096 floats
#define B_STAGE (18 * 4 * 64)     // 4608 floats
#define STAGEF (A_STAGE + B_STAGE)
#define GEMM_SMEM (2 * STAGEF * 4)  // 69632 B

// Mainloop body as a macro-like inline: accumulates into acc given base ptrs.
__device__ __forceinline__ void gemm_mainloop(
    const float* __restrict__ Aap, const float* __restrict__ Bbp,
    float* sm, int rb0, int cb0, int tid, int wm, int wn, int lane,
    float acc[2][9][4])
{
    const uint32_t sbase = (uint32_t)__cvta_generic_to_shared(sm);
    const int T = DIM / BK;   // 40

    auto issue = [&](int stage, int kt) {
        const int kb0 = kt >> 3;
        const uint32_t base = sbase + (uint32_t)stage * STAGEF * 4u;
#pragma unroll
        for (int t = 0; t < 4; t++) {
            int ci = tid + t * 256;
            int blk = ci >> 5;
            int rb_l = blk >> 2, kb_l = blk & 3;
            int l16 = ci & 31;
            cp16(base + (uint32_t)(blk * 128 + l16 * 4) * 4u,
                 Aap + ((size_t)(rb0 + rb_l) * KBX + kb0 + kb_l) * 128 + l16 * 4);
        }
#pragma unroll
        for (int t = 0; t < 5; t++) {
            int ci = tid + t * 256;
            if (ci < 1152) {
                int blk = ci >> 4;
                int cb_l = blk >> 2, kb_l = blk & 3;
                int l16 = ci & 15;
                cp16(base + (uint32_t)(A_STAGE + blk * 64 + l16 * 4) * 4u,
                     Bbp + ((size_t)(cb0 + cb_l) * KBX + kb0 + kb_l) * 64 + l16 * 4);
            }
        }
        asm volatile("cp.async.commit_group;\n");
    };

    auto loadA = [&](const float* Asr, int ks, uint32_t af[2][4]) {
#pragma unroll
        for (int mt = 0; mt < 2; mt++) {
            float4 v = *(const float4*)(Asr + ((wm * 2 + mt) * 4 + ks) * 128 + lane * 4);
            af[mt][0] = __float_as_uint(v.x);
            af[mt][1] = __float_as_uint(v.y);
            af[mt][2] = __float_as_uint(v.z);
            af[mt][3] = __float_as_uint(v.w);
        }
    };
    auto loadB = [&](const float* Bsr, int ks, uint32_t bf[9][2]) {
#pragma unroll
        for (int nt = 0; nt < 9; nt++) {
            float2 v = *(const float2*)(Bsr + ((wn * 9 + nt) * 4 + ks) * 64 + lane * 2);
            bf[nt][0] = __float_as_uint(v.x);
            bf[nt][1] = __float_as_uint(v.y);
        }
    };

    issue(0, 0);

    for (int ti = 0; ti < T; ti++) {
        if (ti + 1 < T) {
            issue((ti + 1) & 1, (ti + 1) * BK);
            asm volatile("cp.async.wait_group 1;\n");
        } else {
            asm volatile("cp.async.wait_group 0;\n");
        }
        __syncthreads();

        const float* Asr = sm + (ti & 1) * STAGEF;
        const float* Bsr = Asr + A_STAGE;

        uint32_t afa[2][4], bfa[9][2], afb[2][4], bfb[9][2];
        loadA(Asr, 0, afa);
        loadB(Bsr, 0, bfa);
#pragma unroll
        for (int ks = 0; ks < 4; ks++) {
            uint32_t (*afc)[4] = (ks & 1) ? afb : afa;
            uint32_t (*bfc)[2] = (ks & 1) ? bfb : bfa;
            uint32_t (*afn)[4] = (ks & 1) ? afa : afb;
            uint32_t (*bfn)[2] = (ks & 1) ? bfa : bfb;
            if (ks < 3) {
                loadA(Asr, ks + 1, afn);
                loadB(Bsr, ks + 1, bfn);
            }
#pragma unroll
            for (int mt = 0; mt < 2; mt++)
#pragma unroll
                for (int nt = 0; nt < 9; nt++)
                    mma_tf32(acc[mt][nt], afc[mt], bfc[nt]);
        }
        __syncthreads();
    }
}

// ---------------------------------------------------------------------------
// Fused QKV GEMM: B = stacked Wq|Wk|Wv fragments (3*162 col-blocks).
// grid (27,16) = 432 CTAs = exactly 3 waves of 144. Tile seg routes output:
// seg 0 -> g_Q, 1 -> g_K, 2 -> g_Vt (transposed + tf32).
// ---------------------------------------------------------------------------
__global__ __launch_bounds__(256, 1)
void gemm_qkv(const float* __restrict__ Aap,
              const float* __restrict__ bq, const float* __restrict__ bk,
              const float* __restrict__ bv)
{
    extern __shared__ float sm[];
    const int tid = threadIdx.x;
    const int m0 = blockIdx.y * BM;
    const int rb0 = m0 >> 4;
    const int cb0 = blockIdx.x * 18;

    const int warp = tid >> 5, lane = tid & 31;
    const int wm = warp >> 1, wn = warp & 1;
    const int g = lane >> 2, tg = lane & 3;

    float acc[2][9][4];
#pragma unroll
    for (int mt = 0; mt < 2; mt++)
#pragma unroll
        for (int nt = 0; nt < 9; nt++)
#pragma unroll
            for (int r = 0; r < 4; r++) acc[mt][nt][r] = 0.f;

    gemm_mainloop(Aap, g_Wqkvp, sm, rb0, cb0, tid, wm, wn, lane, acc);

    const int seg = blockIdx.x / 9;                 // 0:Q 1:K 2:V
    const int n0 = (blockIdx.x - seg * 9) * BN;     // local column base
    const float* bias = (seg == 0) ? bq : (seg == 1) ? bk : bv;
    float* Crow = (seg == 0) ? g_Q : g_K;

#pragma unroll
    for (int mt = 0; mt < 2; mt++) {
#pragma unroll
        for (int nt = 0; nt < 9; nt++) {
            int r = m0 + wm * 32 + mt * 16 + g;
            int c = n0 + wn * 72 + nt * 8 + 2 * tg;
            float b0 = (c < DIM)     ? bias[c]     : 0.f;
            float b1 = (c + 1 < DIM) ? bias[c + 1] : 0.f;
            if (seg < 2) {
                if (c < DIM) {
                    Crow[(size_t)r * DIM + c]       = acc[mt][nt][0] + b0;
                    Crow[(size_t)(r + 8) * DIM + c] = acc[mt][nt][2] + b0;
                }
                if (c + 1 < DIM) {
                    Crow[(size_t)r * DIM + c + 1]       = acc[mt][nt][1] + b1;
                    Crow[(size_t)(r + 8) * DIM + c + 1] = acc[mt][nt][3] + b1;
                }
            } else {
                if (c < DIM) {
                    g_Vt[(size_t)c * SEQ + r]     = f2tf32(acc[mt][nt][0] + b0);
                    g_Vt[(size_t)c * SEQ + r + 8] = f2tf32(acc[mt][nt][2] + b0);
                }
                if (c + 1 < DIM) {
                    g_Vt[(size_t)(c + 1) * SEQ + r]     = f2tf32(acc[mt][nt][1] + b1);
                    g_Vt[(size_t)(c + 1) * SEQ + r + 8] = f2tf32(acc[mt][nt][3] + b1);
                }
            }
        }
    }
}

// ---------------------------------------------------------------------------
// O-projection GEMM (row-major out, no TRANS).
// ---------------------------------------------------------------------------
__global__ __launch_bounds__(256, 1)
void gemm_o(const float* __restrict__ Aap, const float* __restrict__ bias,
            float* __restrict__ C)
{
    extern __shared__ float sm[];
    const int tid = threadIdx.x;
    const int m0 = blockIdx.y * BM;
    const int n0 = blockIdx.x * BN;
    const int rb0 = m0 >> 4;
    const int cb0 = blockIdx.x * 18;

    const int warp = tid >> 5, lane = tid & 31;
    const int wm = warp >> 1, wn = warp & 1;
    const int g = lane >> 2, tg = lane & 3;

    float acc[2][9][4];
#pragma unroll
    for (int mt = 0; mt < 2; mt++)
#pragma unroll
        for (int nt = 0; nt < 9; nt++)
#pragma unroll
            for (int r = 0; r < 4; r++) acc[mt][nt][r] = 0.f;

    gemm_mainloop(Aap, g_Wop, sm, rb0, cb0, tid, wm, wn, lane, acc);

#pragma unroll
    for (int mt = 0; mt < 2; mt++) {
#pragma unroll
        for (int nt = 0; nt < 9; nt++) {
            int r = m0 + wm * 32 + mt * 16 + g;
            int c = n0 + wn * 72 + nt * 8 + 2 * tg;
            float b0 = (c < DIM)     ? bias[c]     : 0.f;
            float b1 = (c + 1 < DIM) ? bias[c + 1] : 0.f;
            if (c < DIM) {
                C[(size_t)r * DIM + c]       = acc[mt][nt][0] + b0;
                C[(size_t)(r + 8) * DIM + c] = acc[mt][nt][2] + b0;
            }
            if (c + 1 < DIM) {
                C[(size_t)r * DIM + c + 1]       = acc[mt][nt][1] + b1;
                C[(size_t)(r + 8) * DIM + c + 1] = acc[mt][nt][3] + b1;
            }
        }
    }
}

// ---------------------------------------------------------------------------
// RoPE in place on g_Q / g_K, float4-vectorized. Q pre-scaled; tf32-rounded.
// ---------------------------------------------------------------------------
__global__ void rope_kernel(const float* __restrict__ cs, const float* __restrict__ sn)
{
    int idx = blockIdx.x * blockDim.x + threadIdx.x;
    const int total = SEQ * NH * 10;
    if (idx >= total) return;
    int j4 = (idx % 10) * 4;
    int h = (idx / 10) % NH;
    int s = idx / (10 * NH);
    int base = s * DIM + h * HD;
    const float scale = rsqrtf((float)HD);

    float4 c0 = *(const float4*)(cs + s * HD + j4);
    float4 c1 = *(const float4*)(cs + s * HD + j4 + 40);
    float4 s0 = *(const float4*)(sn + s * HD + j4);
    float4 s1 = *(const float4*)(sn + s * HD + j4 + 40);

    {
        float4 x0 = *(const float4*)(g_Q + base + j4);
        float4 x1 = *(const float4*)(g_Q + base + j4 + 40);
        float4 o0, o1;
        o0.x = f2tf32((x0.x * c0.x - x1.x * s0.x) * scale);
        o0.y = f2tf32((x0.y * c0.y - x1.y * s0.y) * scale);
        o0.z = f2tf32((x0.z * c0.z - x1.z * s0.z) * scale);
        o0.w = f2tf32((x0.w * c0.w - x1.w * s0.w) * scale);
        o1.x = f2tf32((x1.x * c1.x + x0.x * s1.x) * scale);
        o1.y = f2tf32((x1.y * c1.y + x0.y * s1.y) * scale);
        o1.z = f2tf32((x1.z * c1.z + x0.z * s1.z) * scale);
        o1.w = f2tf32((x1.w * c1.w + x0.w * s1.w) * scale);
        *(float4*)(g_Q + base + j4)      = o0;
        *(float4*)(g_Q + base + j4 + 40) = o1;
    }
    {
        float4 x0 = *(const float4*)(g_K + base + j4);
        float4 x1 = *(const float4*)(g_K + base + j4 + 40);
        float4 o0, o1;
        o0.x = f2tf32(x0.x * c0.x - x1.x * s0.x);
        o0.y = f2tf32(x0.y * c0.y - x1.y * s0.y);
        o0.z = f2tf32(x0.z * c0.z - x1.z * s0.z);
        o0.w = f2tf32(x0.w * c0.w - x1.w * s0.w);
        o1.x = f2tf32(x1.x * c1.x + x0.x * s1.x);
        o1.y = f2tf32(x1.y * c1.y + x0.y * s1.y);
        o1.z = f2tf32(x1.z * c1.z + x0.z * s1.z);
        o1.w = f2tf32(x1.w * c1.w + x0.w * s1.w);
        *(float4*)(g_K + base + j4)      = o0;
        *(float4*)(g_K + base + j4 + 40) = o1;
    }
}

// ---------------------------------------------------------------------------
// Persistent segmented flash attention (proven core). Epilogue writes the
// output in A-fragment order to g_Aap via a warp-private bounce through Qs.
// ---------------------------------------------------------------------------
#define ATT_GRID 296
#define QS_STR 84
#define VT_STR 68
#define AT_KS  (64 * QS_STR)
#define AT_VT  (2 * 64 * QS_STR)
#define AT_PS  (AT_VT + 80 * VT_STR)
#define ATTN_SMEM ((AT_PS + 64 * VT_STR) * 4)   // 82176 B

__global__ __launch_bounds__(128)
void attn_mma(const int* __restrict__ cu)
{
    extern __shared__ float sm[];
    float* Qs = sm;
    float* Ks = sm + AT_KS;
    float* Vt = sm + AT_VT;
    float* Ps = sm + AT_PS;

    const uint32_t sQ = (uint32_t)__cvta_generic_to_shared(Qs);
    const uint32_t sK = (uint32_t)__cvta_generic_to_shared(Ks);
    const uint32_t sV = (uint32_t)__cvta_generic_to_shared(Vt);

    const int tid = threadIdx.x;
    const int warp = tid >> 5, lane = tid & 31;
    const int g = lane >> 2, tg = lane & 3;
    const int m0 = warp * 16;

    for (int item = blockIdx.x; item < (SEQ / 64) * NH; item += ATT_GRID) {
        const int qb = (item >> 4) * 64;
        const int h  = item & 15;

        int ks = 0, ke = SEQ;
#pragma unroll
        for (int i = 0; i < 4; i++)
            if (qb >= cu[i] && qb < cu[i + 1]) { ks = cu[i]; ke = cu[i + 1]; }

        __syncthreads();

#pragma unroll
        for (int t = 0; t < 10; t++) {
            int idx = tid + t * 128;
            int r = idx / 20, dc = (idx % 20) * 4;
            cp16(sQ + (uint32_t)(r * QS_STR + dc) * 4u,
                 g_Q + (size_t)(qb + r) * DIM + h * HD + dc);
        }
        asm volatile("cp.async.commit_group;\n");
        {
            int kn0 = min(64, ke - ks);
#pragma unroll
            for (int t = 0; t < 10; t++) {
                int idx = tid + t * 128;
                int r = idx / 20, dc = (idx % 20) * 4;
                int srow = (r < kn0) ? (ks + r) : ks;
                cp16z(sK + (uint32_t)(r * QS_STR + dc) * 4u,
                      g_K + (size_t)srow * DIM + h * HD + dc, (r < kn0) ? 16 : 0);
            }
            asm volatile("cp.async.commit_group;\n");
        }

        float mrow[2] = {-1e30f, -1e30f};
        float lrow[2] = {0.f, 0.f};
        float o[10][4];
#pragma unroll
        for (int nt = 0; nt < 10; nt++)
#pragma unroll
            for (int r = 0; r < 4; r++) o[nt][r] = 0.f;

        for (int kt = ks; kt < ke; kt += 64) {
            int kn = min(64, ke - kt);
            asm volatile("cp.async.wait_group 0;\n");
            __syncthreads();

#pragma unroll
            for (int t = 0; t < 10; t++) {
                int idx = tid + t * 128;
                int d = idx >> 4, kc = (idx & 15) * 4;
                int bytes = min(max(kn - kc, 0), 4) * 4;
                int scol = (kc < kn) ? (kt + kc) : kt;
                cp16z(sV + (uint32_t)(d * VT_STR + kc) * 4u,
                      g_Vt + (size_t)(h * HD + d) * SEQ + scol, bytes);
            }
            asm volatile("cp.async.commit_group;\n");

            float sacc[8][4];
#pragma unroll
            for (int nt = 0; nt < 8; nt++)
#pragma unroll
                for (int r = 0; r < 4; r++) sacc[nt][r] = 0.f;

#pragma unroll
            for (int ksp = 0; ksp < 10; ksp++) {
                const int k0 = ksp * 8;
                uint32_t af[4], bf[8][2];
                af[0] = __float_as_uint(Qs[(m0 + g) * QS_STR + k0 + tg]);
                af[1] = __float_as_uint(Qs[(m0 + 8 + g) * QS_STR + k0 + tg]);
                af[2] = __float_as_uint(Qs[(m0 + g) * QS_STR + k0 + tg + 4]);
                af[3] = __float_as_uint(Qs[(m0 + 8 + g) * QS_STR + k0 + tg + 4]);
#pragma unroll
                for (int nt = 0; nt < 8; nt++) {
                    bf[nt][0] = __float_as_uint(Ks[(nt * 8 + g) * QS_STR + k0 + tg]);
                    bf[nt][1] = __float_as_uint(Ks[(nt * 8 + g) * QS_STR + k0 + tg + 4]);
                }
#pragma unroll
                for (int nt = 0; nt < 8; nt++)
                    mma_tf32(sacc[nt], af, bf[nt]);
            }

            __syncthreads();

            if (kt + 64 < ke) {
                int knn = min(64, ke - (kt + 64));
#pragma unroll
                for (int t = 0; t < 10; t++) {
                    int idx = tid + t * 128;
                    int r = idx / 20, dc = (idx % 20) * 4;
                    int srow = (r < knn) ? (kt + 64 + r) : (kt + 64 - 1);
                    cp16z(sK + (uint32_t)(r * QS_STR + dc) * 4u,
                          g_K + (size_t)srow * DIM + h * HD + dc, (r < knn) ? 16 : 0);
                }
            }
            asm volatile("cp.async.commit_group;\n");

            if (kn < 64) {
#pragma unroll
                for (int nt = 0; nt < 8; nt++) {
                    int c = nt * 8 + 2 * tg;
                    if (c >= kn)     { sacc[nt][0] = -1e30f; sacc[nt][2] = -1e30f; }
                    if (c + 1 >= kn) { sacc[nt][1] = -1e30f; sacc[nt][3] = -1e30f; }
                }
            }

#pragma unroll
            for (int half = 0; half < 2; half++) {
                const int b = half * 2;
                float mloc = -1e30f;
#pragma unroll
                for (int nt = 0; nt < 8; nt++)
                    mloc = fmaxf(mloc, fmaxf(sacc[nt][b], sacc[nt][b + 1]));
                mloc = fmaxf(mloc, __shfl_xor_sync(0xffffffffu, mloc, 1));
                mloc = fmaxf(mloc, __shfl_xor_sync(0xffffffffu, mloc, 2));
                float mn = fmaxf(mrow[half], mloc);
                float fac = __expf(mrow[half] - mn);
                mrow[half] = mn;
                float rs = 0.f;
#pragma unroll
                for (int nt = 0; nt < 8; nt++) {
                    float p0 = __expf(sacc[nt][b] - mn);
                    float p1 = __expf(sacc[nt][b + 1] - mn);
                    sacc[nt][b] = p0; sacc[nt][b + 1] = p1;
                    rs += p0 + p1;
                }
                rs += __shfl_xor_sync(0xffffffffu, rs, 1);
                rs += __shfl_xor_sync(0xffffffffu, rs, 2);
                lrow[half] = lrow[half] * fac + rs;
#pragma unroll
                for (int nt = 0; nt < 10; nt++) { o[nt][b] *= fac; o[nt][b + 1] *= fac; }
            }

#pragma unroll
            for (int nt = 0; nt < 8; nt++) {
                int c = nt * 8 + 2 * tg;
                Ps[(m0 + g) * VT_STR + c]         = f2tf32(sacc[nt][0]);
                Ps[(m0 + g) * VT_STR + c + 1]     = f2tf32(sacc[nt][1]);
                Ps[(m0 + 8 + g) * VT_STR + c]     = f2tf32(sacc[nt][2]);
                Ps[(m0 + 8 + g) * VT_STR + c + 1] = f2tf32(sacc[nt][3]);
            }

            asm volatile("cp.async.wait_group 1;\n");
            __syncthreads();

#pragma unroll
            for (int ksp = 0; ksp < 8; ksp++) {
                const int k0 = ksp * 8;
                uint32_t af[4], bf[10][2];
                af[0] = __float_as_uint(Ps[(m0 + g) * VT_STR + k0 + tg]);
                af[1] = __float_as_uint(Ps[(m0 + 8 + g) * VT_STR + k0 + tg]);
                af[2] = __float_as_uint(Ps[(m0 + g) * VT_STR + k0 + tg + 4]);
                af[3] = __float_as_uint(Ps[(m0 + 8 + g) * VT_STR + k0 + tg + 4]);
#pragma unroll
                for (int nt = 0; nt < 10; nt++) {
                    bf[nt][0] = __float_as_uint(Vt[(nt * 8 + g) * VT_STR + k0 + tg]);
                    bf[nt][1] = __float_as_uint(Vt[(nt * 8 + g) * VT_STR + k0 + tg + 4]);
                }
#pragma unroll
                for (int nt = 0; nt < 10; nt++)
                    mma_tf32(o[nt], af, bf[nt]);
            }
        }

        const float inv0 = 1.f / lrow[0];
        const float inv1 = 1.f / lrow[1];
#pragma unroll
        for (int nt = 0; nt < 10; nt++) {
            int c = nt * 8 + 2 * tg;
            Qs[(m0 + g) * QS_STR + c]         = o[nt][0] * inv0;
            Qs[(m0 + g) * QS_STR + c + 1]     = o[nt][1] * inv0;
            Qs[(m0 + 8 + g) * QS_STR + c]     = o[nt][2] * inv1;
            Qs[(m0 + 8 + g) * QS_STR + c + 1] = o[nt][3] * inv1;
        }
        __syncwarp();

        const int rb = (qb + m0) >> 4;
#pragma unroll
        for (int nt = 0; nt < 10; nt++) {
            int kb = h * 10 + nt;
            float4 v;
            v.x = f2tf32(Qs[(m0 + g) * QS_STR + nt * 8 + tg]);
            v.y = f2tf32(Qs[(m0 + 8 + g) * QS_STR + nt * 8 + tg]);
            v.z = f2tf32(Qs[(m0 + g) * QS_STR + nt * 8 + tg + 4]);
            v.w = f2tf32(Qs[(m0 + 8 + g) * QS_STR + nt * 8 + tg + 4]);
            ((float4*)g_Aap)[(size_t)(rb * KBX + kb) * 32 + lane] = v;
        }
        __syncwarp();
    }
}

// ---------------------------------------------------------------------------
extern "C" void kernel_launch(void* const* d_in, const int* in_sizes, int n_in,
                              void* d_out, int out_size)
{
    const float* X  = (const float*)d_in[0];
    const float* Wq = (const float*)d_in[1];
    const float* bq = (const float*)d_in[2];
    const float* Wk = (const float*)d_in[3];
    const float* bk = (const float*)d_in[4];
    const float* Wv = (const float*)d_in[5];
    const float* bv = (const float*)d_in[6];
    const float* Wo = (const float*)d_in[7];
    const float* bo = (const float*)d_in[8];
    const float* cs = (const float*)d_in[9];
    const float* sn = (const float*)d_in[10];
    const int*   cu = (const int*)d_in[11];
    float* out = (float*)d_out;

    void *pXap, *pAap;
    cudaGetSymbolAddress(&pXap, g_Xap);
    cudaGetSymbolAddress(&pAap, g_Aap);

    cudaFuncSetAttribute(gemm_qkv,
                         cudaFuncAttributeMaxDynamicSharedMemorySize, GEMM_SMEM);
    cudaFuncSetAttribute(gemm_o,
                         cudaFuncAttributeMaxDynamicSharedMemorySize, GEMM_SMEM);
    cudaFuncSetAttribute(attn_mma,
                         cudaFuncAttributeMaxDynamicSharedMemorySize, ATTN_SMEM);

    const int ntot = NXP + 4 * NWP;

    permute_all<<<(ntot + 255) / 256, 256>>>(X, Wq, Wk, Wv, Wo);

    dim3 gq(27, SEQ / BM);             // 432 CTAs = 3 exact waves of 144
    gemm_qkv<<<gq, 256, GEMM_SMEM>>>((const float*)pXap, bq, bk, bv);

    int rope_total = SEQ * NH * 10;
    rope_kernel<<<(rope_total + 255) / 256, 256>>>(cs, sn);

    attn_mma<<<ATT_GRID, 128, ATTN_SMEM>>>(cu);

    dim3 go(9, SEQ / BM);              // 144 CTAs
    gemm_o<<<go, 256, GEMM_SMEM>>>((const float*)pAap, bo, out);
}

// round 16
// speedup vs baseline: 1.0256x; 1.0078x over previous
#include <cuda_runtime.h>
#include <math.h>
#include <stdint.h>

#define SEQ 2048
#define DIM 1280
#define NH  16
#define HD  80
#define DIMP 1296            // padded weight rows (9 uniform 144-col tiles)
#define RBX (SEQ / 16)       // 128 row-blocks of 16
#define KBX (DIM / 8)        // 160 k-blocks of 8
#define CBW (DIMP / 8)       // 162 col-blocks of 8 (padded)

// Scratch (device globals)
__device__ float g_Q[SEQ * DIM];          // QKV gemm row-major Q (pre-rope)
__device__ float g_K[SEQ * DIM];          // row-major K (pre-rope)
__device__ float g_Qf[SEQ * DIM];         // roped Q, A-fragment order per (rb,h,kb)
__device__ float g_Kf[SEQ * DIM];         // roped K, B-fragment order per (cbk,h,kb)
__device__ float g_Vtf[SEQ * DIM];        // V^T, B-fragment order per (h,db,kb2)
__device__ float g_Xap[SEQ * DIM];        // X in A-fragment order, tf32
__device__ float g_Aap[SEQ * DIM];        // attention out in A-fragment order, tf32
__device__ float g_Wqkvp[3 * DIMP * DIM]; // Wq|Wk|Wv stacked, B-fragment order
__device__ float g_Wop[DIMP * DIM];

__device__ __forceinline__ float f2tf32(float x) {
    uint32_t u;
    asm("cvt.rna.tf32.f32 %0, %1;" : "=r"(u) : "f"(x));
    return __uint_as_float(u);
}

__device__ __forceinline__ void mma_tf32(float* c, const uint32_t* a, const uint32_t* b) {
    asm("mma.sync.aligned.m16n8k8.row.col.f32.tf32.tf32.f32 "
        "{%0,%1,%2,%3}, {%4,%5,%6,%7}, {%8,%9}, {%0,%1,%2,%3};"
        : "+f"(c[0]), "+f"(c[1]), "+f"(c[2]), "+f"(c[3])
        : "r"(a[0]), "r"(a[1]), "r"(a[2]), "r"(a[3]), "r"(b[0]), "r"(b[1]));
}

__device__ __forceinline__ void cp16(uint32_t dst, const void* src) {
    asm volatile("cp.async.cg.shared.global [%0], [%1], 16;\n" :: "r"(dst), "l"(src));
}

// ---------------------------------------------------------------------------
// permute_all: X -> A-fragment order; Wq/Wk/Wv stacked + Wo -> B-frag order.
// ---------------------------------------------------------------------------
#define NXP (RBX * KBX * 32)
#define NWP (CBW * KBX * 32)
__global__ void permute_all(const float* __restrict__ X,
                            const float* __restrict__ Wq, const float* __restrict__ Wk,
                            const float* __restrict__ Wv, const float* __restrict__ Wo)
{
    int i = blockIdx.x * blockDim.x + threadIdx.x;
    if (i < NXP) {
        int lane = i & 31, t = i >> 5;
        int kb = t % KBX, rb = t / KBX;
        int g = lane >> 2, tg = lane & 3;
        int r = rb * 16 + g, c = kb * 8 + tg;
        float4 v;
        v.x = f2tf32(X[(size_t)r * DIM + c]);
        v.y = f2tf32(X[(size_t)(r + 8) * DIM + c]);
        v.z = f2tf32(X[(size_t)r * DIM + c + 4]);
        v.w = f2tf32(X[(size_t)(r + 8) * DIM + c + 4]);
        ((float4*)g_Xap)[i] = v;
        return;
    }
    int j = i - NXP;
    int widx = j / NWP;
    if (widx >= 4) return;
    int k = j - widx * NWP;
    const float* W = (widx == 0) ? Wq : (widx == 1) ? Wk : (widx == 2) ? Wv : Wo;
    float* dst = (widx < 3) ? (g_Wqkvp + (size_t)widx * DIMP * DIM) : g_Wop;
    int lane = k & 31, t = k >> 5;
    int kb = t % KBX, cb = t / KBX;
    int g = lane >> 2, tg = lane & 3;
    int r = cb * 8 + g, c = kb * 8 + tg;
    float2 v;
    if (r < DIM) {
        v.x = f2tf32(W[(size_t)r * DIM + c]);
        v.y = f2tf32(W[(size_t)r * DIM + c + 4]);
    } else {
        v = make_float2(0.f, 0.f);
    }
    ((float2*)dst)[k] = v;
}

// ---------------------------------------------------------------------------
// Shared GEMM mainloop (R13-proven). BM=128, BN=144; 8 warps, tile 32x72.
// ---------------------------------------------------------------------------
#define BM 128
#define BN 144
#define BK 32
#define A_STAGE (8 * 4 * 128)
#define B_STAGE (18 * 4 * 64)
#define STAGEF (A_STAGE + B_STAGE)
#define GEMM_SMEM (2 * STAGEF * 4)

__device__ __forceinline__ void gemm_mainloop(
    const float* __restrict__ Aap, const float* __restrict__ Bbp,
    float* sm, int rb0, int cb0, int tid, int wm, int wn, int lane,
    float acc[2][9][4])
{
    const uint32_t sbase = (uint32_t)__cvta_generic_to_shared(sm);
    const int T = DIM / BK;

    auto issue = [&](int stage, int kt) {
        const int kb0 = kt >> 3;
        const uint32_t base = sbase + (uint32_t)stage * STAGEF * 4u;
#pragma unroll
        for (int t = 0; t < 4; t++) {
            int ci = tid + t * 256;
            int blk = ci >> 5;
            int rb_l = blk >> 2, kb_l = blk & 3;
            int l16 = ci & 31;
            cp16(base + (uint32_t)(blk * 128 + l16 * 4) * 4u,
                 Aap + ((size_t)(rb0 + rb_l) * KBX + kb0 + kb_l) * 128 + l16 * 4);
        }
#pragma unroll
        for (int t = 0; t < 5; t++) {
            int ci = tid + t * 256;
            if (ci < 1152) {
                int blk = ci >> 4;
                int cb_l = blk >> 2, kb_l = blk & 3;
                int l16 = ci & 15;
                cp16(base + (uint32_t)(A_STAGE + blk * 64 + l16 * 4) * 4u,
                     Bbp + ((size_t)(cb0 + cb_l) * KBX + kb0 + kb_l) * 64 + l16 * 4);
            }
        }
        asm volatile("cp.async.commit_group;\n");
    };

    auto loadA = [&](const float* Asr, int ks, uint32_t af[2][4]) {
#pragma unroll
        for (int mt = 0; mt < 2; mt++) {
            float4 v = *(const float4*)(Asr + ((wm * 2 + mt) * 4 + ks) * 128 + lane * 4);
            af[mt][0] = __float_as_uint(v.x);
            af[mt][1] = __float_as_uint(v.y);
            af[mt][2] = __float_as_uint(v.z);
            af[mt][3] = __float_as_uint(v.w);
        }
    };
    auto loadB = [&](const float* Bsr, int ks, uint32_t bf[9][2]) {
#pragma unroll
        for (int nt = 0; nt < 9; nt++) {
            float2 v = *(const float2*)(Bsr + ((wn * 9 + nt) * 4 + ks) * 64 + lane * 2);
            bf[nt][0] = __float_as_uint(v.x);
            bf[nt][1] = __float_as_uint(v.y);
        }
    };

    issue(0, 0);

    for (int ti = 0; ti < T; ti++) {
        if (ti + 1 < T) {
            issue((ti + 1) & 1, (ti + 1) * BK);
            asm volatile("cp.async.wait_group 1;\n");
        } else {
            asm volatile("cp.async.wait_group 0;\n");
        }
        __syncthreads();

        const float* Asr = sm + (ti & 1) * STAGEF;
        const float* Bsr = Asr + A_STAGE;

        uint32_t afa[2][4], bfa[9][2], afb[2][4], bfb[9][2];
        loadA(Asr, 0, afa);
        loadB(Bsr, 0, bfa);
#pragma unroll
        for (int ks = 0; ks < 4; ks++) {
            uint32_t (*afc)[4] = (ks & 1) ? afb : afa;
            uint32_t (*bfc)[2] = (ks & 1) ? bfb : bfa;
            uint32_t (*afn)[4] = (ks & 1) ? afa : afb;
            uint32_t (*bfn)[2] = (ks & 1) ? bfa : bfb;
            if (ks < 3) {
                loadA(Asr, ks + 1, afn);
                loadB(Bsr, ks + 1, bfn);
            }
#pragma unroll
            for (int mt = 0; mt < 2; mt++)
#pragma unroll
                for (int nt = 0; nt < 9; nt++)
                    mma_tf32(acc[mt][nt], afc[mt], bfc[nt]);
        }
        __syncthreads();
    }
}

// ---------------------------------------------------------------------------
// Fused QKV GEMM. seg 0 -> g_Q rows, 1 -> g_K rows, 2 -> g_Vtf fragments.
// ---------------------------------------------------------------------------
__global__ __launch_bounds__(256, 1)
void gemm_qkv(const float* __restrict__ Aap,
              const float* __restrict__ bq, const float* __restrict__ bk,
              const float* __restrict__ bv)
{
    extern __shared__ float sm[];
    const int tid = threadIdx.x;
    const int m0 = blockIdx.y * BM;
    const int rb0 = m0 >> 4;
    const int cb0 = blockIdx.x * 18;

    const int warp = tid >> 5, lane = tid & 31;
    const int wm = warp >> 1, wn = warp & 1;
    const int g = lane >> 2, tg = lane & 3;

    float acc[2][9][4];
#pragma unroll
    for (int mt = 0; mt < 2; mt++)
#pragma unroll
        for (int nt = 0; nt < 9; nt++)
#pragma unroll
            for (int r = 0; r < 4; r++) acc[mt][nt][r] = 0.f;

    gemm_mainloop(Aap, g_Wqkvp, sm, rb0, cb0, tid, wm, wn, lane, acc);

    const int seg = blockIdx.x / 9;
    const int n0 = (blockIdx.x - seg * 9) * BN;
    const float* bias = (seg == 0) ? bq : (seg == 1) ? bk : bv;
    float* Crow = (seg == 0) ? g_Q : g_K;

    auto vtf_store = [&](int key, int c, float val) {
        int h = c / HD, dd = c % HD;
        int db = dd >> 3, gq = dd & 7;
        int kb2 = key >> 3, tgq = key & 7;
        int lanef = gq * 4 + (tgq & 3);
        int comp = (tgq < 4) ? 0 : 1;
        g_Vtf[((((size_t)h * 10 + db) * 256 + kb2) * 32 + lanef) * 2 + comp] = val;
    };

#pragma unroll
    for (int mt = 0; mt < 2; mt++) {
#pragma unroll
        for (int nt = 0; nt < 9; nt++) {
            int r = m0 + wm * 32 + mt * 16 + g;
            int c = n0 + wn * 72 + nt * 8 + 2 * tg;
            float b0 = (c < DIM)     ? bias[c]     : 0.f;
            float b1 = (c + 1 < DIM) ? bias[c + 1] : 0.f;
            if (seg < 2) {
                if (c < DIM) {
                    Crow[(size_t)r * DIM + c]       = acc[mt][nt][0] + b0;
                    Crow[(size_t)(r + 8) * DIM + c] = acc[mt][nt][2] + b0;
                }
                if (c + 1 < DIM) {
                    Crow[(size_t)r * DIM + c + 1]       = acc[mt][nt][1] + b1;
                    Crow[(size_t)(r + 8) * DIM + c + 1] = acc[mt][nt][3] + b1;
                }
            } else {
                if (c < DIM) {
                    vtf_store(r,     c, f2tf32(acc[mt][nt][0] + b0));
                    vtf_store(r + 8, c, f2tf32(acc[mt][nt][2] + b0));
                }
                if (c + 1 < DIM) {
                    vtf_store(r,     c + 1, f2tf32(acc[mt][nt][1] + b1));
                    vtf_store(r + 8, c + 1, f2tf32(acc[mt][nt][3] + b1));
                }
            }
        }
    }
}

// ---------------------------------------------------------------------------
// O-projection GEMM (row-major out).
// ---------------------------------------------------------------------------
__global__ __launch_bounds__(256, 1)
void gemm_o(const float* __restrict__ Aap, const float* __restrict__ bias,
            float* __restrict__ C)
{
    extern __shared__ float sm[];
    const int tid = threadIdx.x;
    const int m0 = blockIdx.y * BM;
    const int n0 = blockIdx.x * BN;
    const int rb0 = m0 >> 4;
    const int cb0 = blockIdx.x * 18;

    const int warp = tid >> 5, lane = tid & 31;
    const int wm = warp >> 1, wn = warp & 1;
    const int g = lane >> 2, tg = lane & 3;

    float acc[2][9][4];
#pragma unroll
    for (int mt = 0; mt < 2; mt++)
#pragma unroll
        for (int nt = 0; nt < 9; nt++)
#pragma unroll
            for (int r = 0; r < 4; r++) acc[mt][nt][r] = 0.f;

    gemm_mainloop(Aap, g_Wop, sm, rb0, cb0, tid, wm, wn, lane, acc);

#pragma unroll
    for (int mt = 0; mt < 2; mt++) {
#pragma unroll
        for (int nt = 0; nt < 9; nt++) {
            int r = m0 + wm * 32 + mt * 16 + g;
            int c = n0 + wn * 72 + nt * 8 + 2 * tg;
            float b0 = (c < DIM)     ? bias[c]     : 0.f;
            float b1 = (c + 1 < DIM) ? bias[c + 1] : 0.f;
            if (c < DIM) {
                C[(size_t)r * DIM + c]       = acc[mt][nt][0] + b0;
                C[(size_t)(r + 8) * DIM + c] = acc[mt][nt][2] + b0;
            }
            if (c + 1 < DIM) {
                C[(size_t)r * DIM + c + 1]       = acc[mt][nt][1] + b1;
                C[(size_t)(r + 8) * DIM + c + 1] = acc[mt][nt][3] + b1;
            }
        }
    }
}

// ---------------------------------------------------------------------------
// RoPE: reads row-major g_Q/g_K, writes FRAGMENT-ORDER g_Qf (A, float4/lane,
// Q pre-scaled) and g_Kf (B, float2/lane). RoPE pair (j, j+40) maps to
// k-blocks kbp and kbp+5 (each fragment touches one half only).
// ---------------------------------------------------------------------------
#define NQP (RBX * NH * 5 * 32)     // 327680
#define NKP ((SEQ / 8) * NH * 5 * 32) // 655360
__global__ void rope_frag(const float* __restrict__ cs, const float* __restrict__ sn)
{
    int i = blockIdx.x * blockDim.x + threadIdx.x;
    const float scale = rsqrtf((float)HD);
    if (i < NQP) {
        int lane = i & 31, t = i >> 5;
        int kbp = t % 5, h = (t / 5) % NH, rbq = t / (5 * NH);
        int g = lane >> 2, tg = lane & 3;
        int r = rbq * 16 + g;
        int cc = kbp * 8 + tg;                 // logical col < 40
        const float* q0 = g_Q + (size_t)r * DIM + h * HD;
        const float* q1 = g_Q + (size_t)(r + 8) * DIM + h * HD;
        float x0[4] = {q0[cc], q1[cc], q0[cc + 4], q1[cc + 4]};
        float x1[4] = {q0[cc + 40], q1[cc + 40], q0[cc + 44], q1[cc + 44]};
        int rr[4] = {r, r + 8, r, r + 8};
        int jc[4] = {cc, cc, cc + 4, cc + 4};
        float4 o0, o1;
        float* o0p = &o0.x; float* o1p = &o1.x;
#pragma unroll
        for (int q = 0; q < 4; q++) {
            float c0 = cs[rr[q] * HD + jc[q]],      s0 = sn[rr[q] * HD + jc[q]];
            float c1 = cs[rr[q] * HD + jc[q] + 40], s1 = sn[rr[q] * HD + jc[q] + 40];
            o0p[q] = f2tf32((x0[q] * c0 - x1[q] * s0) * scale);
            o1p[q] = f2tf32((x1[q] * c1 + x0[q] * s1) * scale);
        }
        size_t base = ((size_t)(rbq * NH + h) * 10);
        ((float4*)g_Qf)[(base + kbp) * 32 + lane] = o0;
        ((float4*)g_Qf)[(base + kbp + 5) * 32 + lane] = o1;
        return;
    }
    int i2 = i - NQP;
    if (i2 >= NKP) return;
    int lane = i2 & 31, t = i2 >> 5;
    int kbp = t % 5, h = (t / 5) % NH, cbk = t / (5 * NH);
    int g = lane >> 2, tg = lane & 3;
    int rk = cbk * 8 + g;
    int cc = kbp * 8 + tg;
    const float* kr = g_K + (size_t)rk * DIM + h * HD;
    float x0[2] = {kr[cc], kr[cc + 4]};
    float x1[2] = {kr[cc + 40], kr[cc + 44]};
    int jc[2] = {cc, cc + 4};
    float2 o0, o1;
    float* o0p = &o0.x; float* o1p = &o1.x;
#pragma unroll
    for (int q = 0; q < 2; q++) {
        float c0 = cs[rk * HD + jc[q]],      s0 = sn[rk * HD + jc[q]];
        float c1 = cs[rk * HD + jc[q] + 40], s1 = sn[rk * HD + jc[q] + 40];
        o0p[q] = f2tf32(x0[q] * c0 - x1[q] * s0);
        o1p[q] = f2tf32(x1[q] * c1 + x0[q] * s1);
    }
    size_t base = ((size_t)(cbk * NH + h) * 10);
    ((float2*)g_Kf)[(base + kbp) * 32 + lane] = o0;
    ((float2*)g_Kf)[(base + kbp + 5) * 32 + lane] = o1;
}

// ---------------------------------------------------------------------------
// Persistent segmented flash attention, FRAGMENT-ORDER operands.
// smem (floats): QF[0,5120) KF[5120,10240) VF[10240,15360) PF[15360,23552).
// S k-step: 1 LDS.128 + 8 LDS.64 (was 20 LDS.32); PV: 1 LDS.128 + 10 LDS.64.
// Output epilogue bounces through scratch (stride 84, overlaps only dead
// QF/KF regions) then writes g_Aap fragments. Values/order == R15.
// ---------------------------------------------------------------------------
#define ATT_GRID 296
#define AF_QF 0
#define AF_KF 5120
#define AF_VF 10240
#define AF_PF 15360
#define ATTN_SMEM (23552 * 4)   // 94208 B

__global__ __launch_bounds__(128)
void attn_mma(const int* __restrict__ cu)
{
    extern __shared__ float smf[];
    const uint32_t sb = (uint32_t)__cvta_generic_to_shared(smf);

    const int tid = threadIdx.x;
    const int warp = tid >> 5, lane = tid & 31;
    const int g = lane >> 2, tg = lane & 3;
    const int m0 = warp * 16;

    for (int item = blockIdx.x; item < (SEQ / 64) * NH; item += ATT_GRID) {
        const int qb = (item >> 4) * 64;
        const int h  = item & 15;
        const int rbq0 = qb >> 4;

        int ks = 0, ke = SEQ;
#pragma unroll
        for (int i = 0; i < 4; i++)
            if (qb >= cu[i] && qb < cu[i + 1]) { ks = cu[i]; ke = cu[i + 1]; }

        __syncthreads();   // prior item's smem readers done

        // Q fill (A fragments): 40 blocks x 128 floats
#pragma unroll
        for (int t = 0; t < 10; t++) {
            int idx = tid + t * 128;
            int blk = idx >> 5;                 // wq*10+kb
            int wq = blk / 10, kb = blk % 10;
            int l16 = idx & 31;
            cp16(sb + (uint32_t)(AF_QF + blk * 128 + l16 * 4) * 4u,
                 g_Qf + ((size_t)((rbq0 + wq) * NH + h) * 10 + kb) * 128 + l16 * 4);
        }
        asm volatile("cp.async.commit_group;\n");
        // first K fill (B fragments): 80 blocks x 64 floats
        {
            int cbk0 = ks >> 3;
#pragma unroll
            for (int t = 0; t < 10; t++) {
                int idx = tid + t * 128;
                int blk = idx >> 4;             // cbk_l*10+kb
                int cbl = blk / 10, kb = blk % 10;
                int l8 = idx & 15;
                cp16(sb + (uint32_t)(AF_KF + blk * 64 + l8 * 4) * 4u,
                     g_Kf + ((size_t)((cbk0 + cbl) * NH + h) * 10 + kb) * 64 + l8 * 4);
            }
            asm volatile("cp.async.commit_group;\n");
        }

        float mrow[2] = {-1e30f, -1e30f};
        float lrow[2] = {0.f, 0.f};
        float o[10][4];
#pragma unroll
        for (int nt = 0; nt < 10; nt++)
#pragma unroll
            for (int r = 0; r < 4; r++) o[nt][r] = 0.f;

        for (int kt = ks; kt < ke; kt += 64) {
            int kn = min(64, ke - kt);
            asm volatile("cp.async.wait_group 0;\n");
            __syncthreads();

            // V fill (B fragments): 80 blocks x 64 floats (overlaps S compute)
            {
                int kb20 = kt >> 3;
#pragma unroll
                for (int t = 0; t < 10; t++) {
                    int idx = tid + t * 128;
                    int blk = idx >> 4;          // db*8+kb2l
                    int db = blk >> 3, kb2l = blk & 7;
                    int l8 = idx & 15;
                    cp16(sb + (uint32_t)(AF_VF + blk * 64 + l8 * 4) * 4u,
                         g_Vtf + ((size_t)(h * 10 + db) * 256 + kb20 + kb2l) * 64 + l8 * 4);
                }
                asm volatile("cp.async.commit_group;\n");
            }

            // S = Q K^T
            float sacc[8][4];
#pragma unroll
            for (int nt = 0; nt < 8; nt++)
#pragma unroll
                for (int r = 0; r < 4; r++) sacc[nt][r] = 0.f;

#pragma unroll
            for (int ksp = 0; ksp < 10; ksp++) {
                uint32_t af[4], bf[8][2];
                float4 av = *(const float4*)(smf + AF_QF + (warp * 10 + ksp) * 128 + lane * 4);
                af[0] = __float_as_uint(av.x);
                af[1] = __float_as_uint(av.y);
                af[2] = __float_as_uint(av.z);
                af[3] = __float_as_uint(av.w);
#pragma unroll
                for (int nt = 0; nt < 8; nt++) {
                    float2 bv = *(const float2*)(smf + AF_KF + (nt * 10 + ksp) * 64 + lane * 2);
                    bf[nt][0] = __float_as_uint(bv.x);
                    bf[nt][1] = __float_as_uint(bv.y);
                }
#pragma unroll
                for (int nt = 0; nt < 8; nt++)
                    mma_tf32(sacc[nt], af, bf[nt]);
            }

            __syncthreads();   // all warps done reading KF (and QF this iter)

            // Issue K_{kt+64}
            if (kt + 64 < ke) {
                int cbk0 = (kt + 64) >> 3;
#pragma unroll
                for (int t = 0; t < 10; t++) {
                    int idx = tid + t * 128;
                    int blk = idx >> 4;
                    int cbl = blk / 10, kb = blk % 10;
                    int l8 = idx & 15;
                    cp16(sb + (uint32_t)(AF_KF + blk * 64 + l8 * 4) * 4u,
                         g_Kf + ((size_t)((cbk0 + cbl) * NH + h) * 10 + kb) * 64 + l8 * 4);
                }
            }
            asm volatile("cp.async.commit_group;\n");

            if (kn < 64) {
#pragma unroll
                for (int nt = 0; nt < 8; nt++) {
                    int c = nt * 8 + 2 * tg;
                    if (c >= kn)     { sacc[nt][0] = -1e30f; sacc[nt][2] = -1e30f; }
                    if (c + 1 >= kn) { sacc[nt][1] = -1e30f; sacc[nt][3] = -1e30f; }
                }
            }

            // Online softmax
#pragma unroll
            for (int half = 0; half < 2; half++) {
                const int b = half * 2;
                float mloc = -1e30f;
#pragma unroll
                for (int nt = 0; nt < 8; nt++)
                    mloc = fmaxf(mloc, fmaxf(sacc[nt][b], sacc[nt][b + 1]));
                mloc = fmaxf(mloc, __shfl_xor_sync(0xffffffffu, mloc, 1));
                mloc = fmaxf(mloc, __shfl_xor_sync(0xffffffffu, mloc, 2));
                float mn = fmaxf(mrow[half], mloc);
                float fac = __expf(mrow[half] - mn);
                mrow[half] = mn;
                float rs = 0.f;
#pragma unroll
                for (int nt = 0; nt < 8; nt++) {
                    float p0 = __expf(sacc[nt][b] - mn);
                    float p1 = __expf(sacc[nt][b + 1] - mn);
                    sacc[nt][b] = p0; sacc[nt][b + 1] = p1;
                    rs += p0 + p1;
                }
                rs += __shfl_xor_sync(0xffffffffu, rs, 1);
                rs += __shfl_xor_sync(0xffffffffu, rs, 2);
                lrow[half] = lrow[half] * fac + rs;
#pragma unroll
                for (int nt = 0; nt < 10; nt++) { o[nt][b] *= fac; o[nt][b + 1] *= fac; }
            }

            // Stage P in A-fragment layout (warp-private PF region)
            {
                float* pw = smf + AF_PF + warp * 2048;
                const int jj = 2 * tg;
                const int l0 = g * 4 + (jj & 3);
                const int l1 = g * 4 + ((jj + 1) & 3);
                const int cb = (tg < 2) ? 0 : 2;
#pragma unroll
                for (int nt = 0; nt < 8; nt++) {
                    pw[nt * 128 + l0 * 4 + cb]     = f2tf32(sacc[nt][0]);
                    pw[nt * 128 + l1 * 4 + cb]     = f2tf32(sacc[nt][1]);
                    pw[nt * 128 + l0 * 4 + cb + 1] = f2tf32(sacc[nt][2]);
                    pw[nt * 128 + l1 * 4 + cb + 1] = f2tf32(sacc[nt][3]);
                }
            }
            __syncwarp();

            // Wait V (newest group = next-K may still be in flight)
            asm volatile("cp.async.wait_group 1;\n");
            __syncthreads();

            // O += P V
#pragma unroll
            for (int ksp = 0; ksp < 8; ksp++) {
                uint32_t af[4], bf[10][2];
                float4 av = *(const float4*)(smf + AF_PF + warp * 2048 + ksp * 128 + lane * 4);
                af[0] = __float_as_uint(av.x);
                af[1] = __float_as_uint(av.y);
                af[2] = __float_as_uint(av.z);
                af[3] = __float_as_uint(av.w);
#pragma unroll
                for (int nt = 0; nt < 10; nt++) {
                    float2 bv = *(const float2*)(smf + AF_VF + (nt * 8 + ksp) * 64 + lane * 2);
                    bf[nt][0] = __float_as_uint(bv.x);
                    bf[nt][1] = __float_as_uint(bv.y);
                }
#pragma unroll
                for (int nt = 0; nt < 10; nt++)
                    mma_tf32(o[nt], af, bf[nt]);
            }
        }

        // Epilogue: scratch stride 84 at smem base (overlaps only dead QF/KF).
        const float inv0 = 1.f / lrow[0];
        const float inv1 = 1.f / lrow[1];
#pragma unroll
        for (int nt = 0; nt < 10; nt++) {
            int c = nt * 8 + 2 * tg;
            smf[(m0 + g) * 84 + c]         = o[nt][0] * inv0;
            smf[(m0 + g) * 84 + c + 1]     = o[nt][1] * inv0;
            smf[(m0 + 8 + g) * 84 + c]     = o[nt][2] * inv1;
            smf[(m0 + 8 + g) * 84 + c + 1] = o[nt][3] * inv1;
        }
        __syncwarp();

        const int rb = (qb + m0) >> 4;
#pragma unroll
        for (int nt = 0; nt < 10; nt++) {
            int kb = h * 10 + nt;
            float4 v;
            v.x = f2tf32(smf[(m0 + g) * 84 + nt * 8 + tg]);
            v.y = f2tf32(smf[(m0 + 8 + g) * 84 + nt * 8 + tg]);
            v.z = f2tf32(smf[(m0 + g) * 84 + nt * 8 + tg + 4]);
            v.w = f2tf32(smf[(m0 + 8 + g) * 84 + nt * 8 + tg + 4]);
            ((float4*)g_Aap)[(size_t)(rb * KBX + kb) * 32 + lane] = v;
        }
        __syncwarp();
    }
}

// ---------------------------------------------------------------------------
extern "C" void kernel_launch(void* const* d_in, const int* in_sizes, int n_in,
                              void* d_out, int out_size)
{
    const float* X  = (const float*)d_in[0];
    const float* Wq = (const float*)d_in[1];
    const float* bq = (const float*)d_in[2];
    const float* Wk = (const float*)d_in[3];
    const float* bk = (const float*)d_in[4];
    const float* Wv = (const float*)d_in[5];
    const float* bv = (const float*)d_in[6];
    const float* Wo = (const float*)d_in[7];
    const float* bo = (const float*)d_in[8];
    const float* cs = (const float*)d_in[9];
    const float* sn = (const float*)d_in[10];
    const int*   cu = (const int*)d_in[11];
    float* out = (float*)d_out;

    void *pXap, *pAap;
    cudaGetSymbolAddress(&pXap, g_Xap);
    cudaGetSymbolAddress(&pAap, g_Aap);

    cudaFuncSetAttribute(gemm_qkv,
                         cudaFuncAttributeMaxDynamicSharedMemorySize, GEMM_SMEM);
    cudaFuncSetAttribute(gemm_o,
                         cudaFuncAttributeMaxDynamicSharedMemorySize, GEMM_SMEM);
    cudaFuncSetAttribute(attn_mma,
                         cudaFuncAttributeMaxDynamicSharedMemorySize, ATTN_SMEM);

    const int ntot = NXP + 4 * NWP;

    permute_all<<<(ntot + 255) / 256, 256>>>(X, Wq, Wk, Wv, Wo);

    dim3 gq(27, SEQ / BM);             // 432 CTAs = 3 exact waves of 144
    gemm_qkv<<<gq, 256, GEMM_SMEM>>>((const float*)pXap, bq, bk, bv);

    const int rtot = NQP + NKP;
    rope_frag<<<(rtot + 255) / 256, 256>>>(cs, sn);

    attn_mma<<<ATT_GRID, 128, ATTN_SMEM>>>(cu);

    dim3 go(9, SEQ / BM);              // 144 CTAs
    gemm_o<<<go, 256, GEMM_SMEM>>>((const float*)pAap, bo, out);
}